// round 1
// baseline (speedup 1.0000x reference)
#include <cuda_runtime.h>
#include <math.h>

#define B_SZ   2
#define S_LEN  2048
#define E_DIM  1024
#define H_NUM  16
#define D_HEAD 64
#define QKV_DIM 3072   // 3 * E_DIM

// Scratch (allocation-free rule: device globals)
__device__ float g_qkv[B_SZ * S_LEN * QKV_DIM];   // [B,S,3E]
__device__ float g_attn[B_SZ * S_LEN * E_DIM];    // [B,S,E]

// ---------------------------------------------------------------------------
// GEMM: C[M,N] = A[M,K] @ W[N,K]^T + bias[N]
// BM=BN=128, BK=16, 256 threads, 8x8 per thread, register-prefetch pipelining.
// ---------------------------------------------------------------------------
__global__ __launch_bounds__(256)
void gemm_nt_bias(const float* __restrict__ A, const float* __restrict__ W,
                  const float* __restrict__ bias, float* __restrict__ C,
                  int M, int N, int K)
{
    __shared__ float As[16][128];   // As[k][m]
    __shared__ float Ws[16][128];   // Ws[k][n]

    const int tid = threadIdx.x;
    const int tx  = tid & 15;       // n-dir
    const int ty  = tid >> 4;       // m-dir
    const int m0  = blockIdx.y * 128;
    const int n0  = blockIdx.x * 128;

    const float* Ab = A + (size_t)m0 * K;
    const float* Wb = W + (size_t)n0 * K;

    const int lr = tid >> 2;          // 0..63 (row within tile, +64 second half)
    const int lc = (tid & 3) * 4;     // 0,4,8,12 (k offset)

    float4 pa[2], pw[2];
#pragma unroll
    for (int p = 0; p < 2; p++) {
        pa[p] = *(const float4*)&Ab[(size_t)(lr + p * 64) * K + lc];
        pw[p] = *(const float4*)&Wb[(size_t)(lr + p * 64) * K + lc];
    }

    float acc[8][8];
#pragma unroll
    for (int i = 0; i < 8; i++)
#pragma unroll
        for (int j = 0; j < 8; j++) acc[i][j] = 0.f;

    const int ntiles = K >> 4;
    for (int t = 0; t < ntiles; t++) {
        // commit prefetched tile to smem (transposed)
#pragma unroll
        for (int p = 0; p < 2; p++) {
            const int r = lr + p * 64;
            As[lc + 0][r] = pa[p].x;  As[lc + 1][r] = pa[p].y;
            As[lc + 2][r] = pa[p].z;  As[lc + 3][r] = pa[p].w;
            Ws[lc + 0][r] = pw[p].x;  Ws[lc + 1][r] = pw[p].y;
            Ws[lc + 2][r] = pw[p].z;  Ws[lc + 3][r] = pw[p].w;
        }
        __syncthreads();

        if (t + 1 < ntiles) {
            const int ko = (t + 1) * 16 + lc;
#pragma unroll
            for (int p = 0; p < 2; p++) {
                pa[p] = *(const float4*)&Ab[(size_t)(lr + p * 64) * K + ko];
                pw[p] = *(const float4*)&Wb[(size_t)(lr + p * 64) * K + ko];
            }
        }

#pragma unroll
        for (int k = 0; k < 16; k++) {
            const float4 a0 = *(const float4*)&As[k][ty * 8];
            const float4 a1 = *(const float4*)&As[k][ty * 8 + 4];
            const float4 b0 = *(const float4*)&Ws[k][tx * 8];
            const float4 b1 = *(const float4*)&Ws[k][tx * 8 + 4];
            const float av[8] = {a0.x, a0.y, a0.z, a0.w, a1.x, a1.y, a1.z, a1.w};
            const float bv[8] = {b0.x, b0.y, b0.z, b0.w, b1.x, b1.y, b1.z, b1.w};
#pragma unroll
            for (int i = 0; i < 8; i++)
#pragma unroll
                for (int j = 0; j < 8; j++)
                    acc[i][j] = fmaf(av[i], bv[j], acc[i][j]);
        }
        __syncthreads();
    }

    const float4 bs0 = *(const float4*)&bias[n0 + tx * 8];
    const float4 bs1 = *(const float4*)&bias[n0 + tx * 8 + 4];
    const float bb[8] = {bs0.x, bs0.y, bs0.z, bs0.w, bs1.x, bs1.y, bs1.z, bs1.w};
#pragma unroll
    for (int i = 0; i < 8; i++) {
        const size_t row = (size_t)(m0 + ty * 8 + i);
        float4 c0, c1;
        c0.x = acc[i][0] + bb[0]; c0.y = acc[i][1] + bb[1];
        c0.z = acc[i][2] + bb[2]; c0.w = acc[i][3] + bb[3];
        c1.x = acc[i][4] + bb[4]; c1.y = acc[i][5] + bb[5];
        c1.z = acc[i][6] + bb[6]; c1.w = acc[i][7] + bb[7];
        *(float4*)&C[row * N + n0 + tx * 8]     = c0;
        *(float4*)&C[row * N + n0 + tx * 8 + 4] = c1;
    }
}

// ---------------------------------------------------------------------------
// Flash attention: one block per (b, h, 64-q-row tile). 256 threads (16x16),
// 4x4 microtile per thread. Online softmax, P staged through smem.
// ---------------------------------------------------------------------------
#define AT_STRIDE 68   // 64 + pad 4

__global__ __launch_bounds__(256)
void attn_kernel(const float* __restrict__ qkv, float* __restrict__ out)
{
    extern __shared__ float sm[];
    float* Qst = sm;                        // [64 d][68] Q^T, scaled
    float* Kt  = sm + 64 * AT_STRIDE;       // [64 d][68] K^T
    float* Vs  = sm + 2 * 64 * AT_STRIDE;   // [64 j][68] V
    float* Ps  = sm + 3 * 64 * AT_STRIDE;   // [64 i][68] P

    const int tid = threadIdx.x;
    const int tx  = tid & 15;   // col (j / d-out) group
    const int ty  = tid >> 4;   // row (i) group
    const int q0  = blockIdx.x * 64;
    const int h   = blockIdx.y;
    const int b   = blockIdx.z;
    const float scale = 0.125f;   // 1/sqrt(64)

    const size_t bh = (size_t)b * S_LEN * QKV_DIM + (size_t)h * (3 * D_HEAD);

    // Load Q tile transposed & pre-scaled
    for (int idx = tid; idx < 64 * 16; idx += 256) {
        const int i = idx >> 4;
        const int d = (idx & 15) * 4;
        const float4 q = *(const float4*)&qkv[bh + (size_t)(q0 + i) * QKV_DIM + d];
        Qst[(d + 0) * AT_STRIDE + i] = q.x * scale;
        Qst[(d + 1) * AT_STRIDE + i] = q.y * scale;
        Qst[(d + 2) * AT_STRIDE + i] = q.z * scale;
        Qst[(d + 3) * AT_STRIDE + i] = q.w * scale;
    }

    float o[4][4];
#pragma unroll
    for (int i = 0; i < 4; i++)
#pragma unroll
        for (int j = 0; j < 4; j++) o[i][j] = 0.f;
    float m[4] = {-INFINITY, -INFINITY, -INFINITY, -INFINITY};
    float l[4] = {0.f, 0.f, 0.f, 0.f};

    for (int kt = 0; kt < S_LEN / 64; kt++) {
        __syncthreads();   // prior PV done before overwriting K/V
        const int j0 = kt * 64;
        for (int idx = tid; idx < 64 * 16; idx += 256) {
            const int j = idx >> 4;
            const int d = (idx & 15) * 4;
            const size_t base = bh + (size_t)(j0 + j) * QKV_DIM + d;
            const float4 kk = *(const float4*)&qkv[base + D_HEAD];       // K
            const float4 vv = *(const float4*)&qkv[base + 2 * D_HEAD];   // V
            Kt[(d + 0) * AT_STRIDE + j] = kk.x;
            Kt[(d + 1) * AT_STRIDE + j] = kk.y;
            Kt[(d + 2) * AT_STRIDE + j] = kk.z;
            Kt[(d + 3) * AT_STRIDE + j] = kk.w;
            *(float4*)&Vs[j * AT_STRIDE + d] = vv;
        }
        __syncthreads();

        // S = (Q*scale) @ K^T  (outer product over d)
        float s[4][4];
#pragma unroll
        for (int i = 0; i < 4; i++)
#pragma unroll
            for (int j = 0; j < 4; j++) s[i][j] = 0.f;
#pragma unroll 16
        for (int d = 0; d < 64; d++) {
            const float4 qa = *(const float4*)&Qst[d * AT_STRIDE + ty * 4];
            const float4 kb = *(const float4*)&Kt[d * AT_STRIDE + tx * 4];
            const float qv[4] = {qa.x, qa.y, qa.z, qa.w};
            const float kv[4] = {kb.x, kb.y, kb.z, kb.w};
#pragma unroll
            for (int i = 0; i < 4; i++)
#pragma unroll
                for (int j = 0; j < 4; j++)
                    s[i][j] = fmaf(qv[i], kv[j], s[i][j]);
        }

        // Online softmax per row (reduce across the 16 tx lanes)
#pragma unroll
        for (int ii = 0; ii < 4; ii++) {
            float mt = fmaxf(fmaxf(s[ii][0], s[ii][1]), fmaxf(s[ii][2], s[ii][3]));
#pragma unroll
            for (int msk = 1; msk < 16; msk <<= 1)
                mt = fmaxf(mt, __shfl_xor_sync(0xffffffffu, mt, msk));
            const float mn = fmaxf(m[ii], mt);
            const float corr = __expf(m[ii] - mn);
            m[ii] = mn;
            float rs = 0.f;
#pragma unroll
            for (int jj = 0; jj < 4; jj++) {
                const float p = __expf(s[ii][jj] - mn);
                s[ii][jj] = p;
                rs += p;
            }
#pragma unroll
            for (int msk = 1; msk < 16; msk <<= 1)
                rs += __shfl_xor_sync(0xffffffffu, rs, msk);
            l[ii] = l[ii] * corr + rs;
#pragma unroll
            for (int jj = 0; jj < 4; jj++) o[ii][jj] *= corr;
        }

        // stage P
#pragma unroll
        for (int ii = 0; ii < 4; ii++)
#pragma unroll
            for (int jj = 0; jj < 4; jj++)
                Ps[(ty * 4 + ii) * AT_STRIDE + tx * 4 + jj] = s[ii][jj];
        __syncthreads();

        // O += P @ V
#pragma unroll 8
        for (int j = 0; j < 64; j++) {
            const float4 v = *(const float4*)&Vs[j * AT_STRIDE + tx * 4];
            const float p0 = Ps[(ty * 4 + 0) * AT_STRIDE + j];
            const float p1 = Ps[(ty * 4 + 1) * AT_STRIDE + j];
            const float p2 = Ps[(ty * 4 + 2) * AT_STRIDE + j];
            const float p3 = Ps[(ty * 4 + 3) * AT_STRIDE + j];
            o[0][0] = fmaf(p0, v.x, o[0][0]); o[0][1] = fmaf(p0, v.y, o[0][1]);
            o[0][2] = fmaf(p0, v.z, o[0][2]); o[0][3] = fmaf(p0, v.w, o[0][3]);
            o[1][0] = fmaf(p1, v.x, o[1][0]); o[1][1] = fmaf(p1, v.y, o[1][1]);
            o[1][2] = fmaf(p1, v.z, o[1][2]); o[1][3] = fmaf(p1, v.w, o[1][3]);
            o[2][0] = fmaf(p2, v.x, o[2][0]); o[2][1] = fmaf(p2, v.y, o[2][1]);
            o[2][2] = fmaf(p2, v.z, o[2][2]); o[2][3] = fmaf(p2, v.w, o[2][3]);
            o[3][0] = fmaf(p3, v.x, o[3][0]); o[3][1] = fmaf(p3, v.y, o[3][1]);
            o[3][2] = fmaf(p3, v.z, o[3][2]); o[3][3] = fmaf(p3, v.w, o[3][3]);
        }
    }

    // normalize + write [B,S,H*D]
#pragma unroll
    for (int ii = 0; ii < 4; ii++) {
        const float inv = 1.f / l[ii];
        const int row = q0 + ty * 4 + ii;
        float4 r;
        r.x = o[ii][0] * inv; r.y = o[ii][1] * inv;
        r.z = o[ii][2] * inv; r.w = o[ii][3] * inv;
        *(float4*)&out[((size_t)b * S_LEN + row) * E_DIM + h * D_HEAD + tx * 4] = r;
    }
}

// ---------------------------------------------------------------------------
extern "C" void kernel_launch(void* const* d_in, const int* in_sizes, int n_in,
                              void* d_out, int out_size)
{
    const float* x     = (const float*)d_in[0];
    const float* w_qkv = (const float*)d_in[1];
    const float* b_qkv = (const float*)d_in[2];
    const float* w_o   = (const float*)d_in[3];
    const float* b_o   = (const float*)d_in[4];
    float* out = (float*)d_out;

    float* qkv;  cudaGetSymbolAddress((void**)&qkv,  g_qkv);
    float* attn; cudaGetSymbolAddress((void**)&attn, g_attn);

    const int M = B_SZ * S_LEN;   // 4096

    // 1) QKV projection: [4096,1024] @ [3072,1024]^T
    gemm_nt_bias<<<dim3(QKV_DIM / 128, M / 128), 256>>>(
        x, w_qkv, b_qkv, qkv, M, QKV_DIM, E_DIM);

    // 2) Flash attention
    const int attn_smem = 4 * 64 * AT_STRIDE * (int)sizeof(float);  // 69632 B
    cudaFuncSetAttribute(attn_kernel,
                         cudaFuncAttributeMaxDynamicSharedMemorySize, attn_smem);
    attn_kernel<<<dim3(S_LEN / 64, H_NUM, B_SZ), 256, attn_smem>>>(qkv, attn);

    // 3) Output projection: [4096,1024] @ [1024,1024]^T
    gemm_nt_bias<<<dim3(E_DIM / 128, M / 128), 256>>>(
        attn, w_o, b_o, out, M, E_DIM, E_DIM);
}

// round 2
// speedup vs baseline: 3.1312x; 3.1312x over previous
#include <cuda_runtime.h>
#include <math.h>

#define B_SZ   2
#define S_LEN  2048
#define E_DIM  1024
#define H_NUM  16
#define D_HEAD 64
#define QKV_DIM 3072   // 3 * E_DIM

// Scratch (allocation-free rule: device globals)
__device__ float g_qkv[B_SZ * S_LEN * QKV_DIM];   // [B,S,3E]
__device__ float g_attn[B_SZ * S_LEN * E_DIM];    // [B,S,E]

// ---------------------------------------------------------------------------
// helpers
// ---------------------------------------------------------------------------
__device__ __forceinline__ unsigned f2tf(float f) {
    unsigned u;
    asm("cvt.rna.tf32.f32 %0, %1;" : "=r"(u) : "f"(f));
    return u;
}

// D += A(16x8, tf32, row) * B(8x8, tf32, col), fp32 accumulate, in-place
__device__ __forceinline__ void mma8(float* d, const unsigned* a, const unsigned* b) {
    asm volatile(
        "mma.sync.aligned.m16n8k8.row.col.f32.tf32.tf32.f32 "
        "{%0,%1,%2,%3},{%4,%5,%6,%7},{%8,%9},{%0,%1,%2,%3};"
        : "+f"(d[0]), "+f"(d[1]), "+f"(d[2]), "+f"(d[3])
        : "r"(a[0]), "r"(a[1]), "r"(a[2]), "r"(a[3]), "r"(b[0]), "r"(b[1]));
}

// ---------------------------------------------------------------------------
// Tensor-core GEMM: C[M,N] = A[M,K] @ W[N,K]^T + bias[N]
// 128x128x32 tiles, 8 warps, warp tile 64x32 (4x4 of m16n8k8).
// ---------------------------------------------------------------------------
#define GS 36   // smem row stride (36 mod 32 == 4 -> conflict-free frag gathers)

__global__ __launch_bounds__(256)
void gemm_tc(const float* __restrict__ A, const float* __restrict__ W,
             const float* __restrict__ bias, float* __restrict__ C,
             int M, int N, int K)
{
    __shared__ unsigned As[128 * GS];
    __shared__ unsigned Bs[128 * GS];

    const int tid  = threadIdx.x;
    const int lane = tid & 31;
    const int w    = tid >> 5;
    const int wr   = w >> 2;     // 0..1
    const int wc   = w & 3;      // 0..3
    const int g    = lane >> 2;  // 0..7
    const int qp   = lane & 3;   // 0..3
    const int m0   = blockIdx.y * 128;
    const int n0   = blockIdx.x * 128;

    // gmem prefetch: 4 float4 per thread per matrix per BK=32 step
    float4 pa[4], pb[4];
#pragma unroll
    for (int i = 0; i < 4; i++) {
        const int lin = tid + i * 256;
        const int r   = lin >> 3;
        const int c4  = (lin & 7) * 4;
        pa[i] = *(const float4*)&A[(size_t)(m0 + r) * K + c4];
        pb[i] = *(const float4*)&W[(size_t)(n0 + r) * K + c4];
    }

    float acc[4][4][4];
#pragma unroll
    for (int mt = 0; mt < 4; mt++)
#pragma unroll
        for (int nt = 0; nt < 4; nt++)
#pragma unroll
            for (int r = 0; r < 4; r++) acc[mt][nt][r] = 0.f;

    const int niters = K >> 5;
    for (int t = 0; t < niters; t++) {
        // commit prefetched tile to smem (convert to tf32)
#pragma unroll
        for (int i = 0; i < 4; i++) {
            const int lin = tid + i * 256;
            const int r   = lin >> 3;
            const int c4  = (lin & 7) * 4;
            uint4 ua, ub;
            ua.x = f2tf(pa[i].x); ua.y = f2tf(pa[i].y);
            ua.z = f2tf(pa[i].z); ua.w = f2tf(pa[i].w);
            ub.x = f2tf(pb[i].x); ub.y = f2tf(pb[i].y);
            ub.z = f2tf(pb[i].z); ub.w = f2tf(pb[i].w);
            *(uint4*)&As[r * GS + c4] = ua;
            *(uint4*)&Bs[r * GS + c4] = ub;
        }
        __syncthreads();

        if (t + 1 < niters) {
            const int ko = (t + 1) * 32;
#pragma unroll
            for (int i = 0; i < 4; i++) {
                const int lin = tid + i * 256;
                const int r   = lin >> 3;
                const int c4  = (lin & 7) * 4;
                pa[i] = *(const float4*)&A[(size_t)(m0 + r) * K + ko + c4];
                pb[i] = *(const float4*)&W[(size_t)(n0 + r) * K + ko + c4];
            }
        }

#pragma unroll
        for (int ks = 0; ks < 4; ks++) {
            const int kb = ks * 8;
            unsigned af[4][4];
#pragma unroll
            for (int mt = 0; mt < 4; mt++) {
                const int r0 = wr * 64 + mt * 16 + g;
                af[mt][0] = As[r0 * GS + kb + qp];
                af[mt][1] = As[(r0 + 8) * GS + kb + qp];
                af[mt][2] = As[r0 * GS + kb + qp + 4];
                af[mt][3] = As[(r0 + 8) * GS + kb + qp + 4];
            }
            unsigned bf[4][2];
#pragma unroll
            for (int nt = 0; nt < 4; nt++) {
                const int c0 = wc * 32 + nt * 8 + g;
                bf[nt][0] = Bs[c0 * GS + kb + qp];
                bf[nt][1] = Bs[c0 * GS + kb + qp + 4];
            }
#pragma unroll
            for (int mt = 0; mt < 4; mt++)
#pragma unroll
                for (int nt = 0; nt < 4; nt++)
                    mma8(acc[mt][nt], af[mt], bf[nt]);
        }
        __syncthreads();
    }

    // epilogue: bias + store (c-frag layout: rows g,g+8; cols qp*2,qp*2+1)
#pragma unroll
    for (int nt = 0; nt < 4; nt++) {
        const int cc = n0 + wc * 32 + nt * 8 + qp * 2;
        const float2 bb = *(const float2*)&bias[cc];
#pragma unroll
        for (int mt = 0; mt < 4; mt++) {
            const int r = m0 + wr * 64 + mt * 16 + g;
            float2 v0, v1;
            v0.x = acc[mt][nt][0] + bb.x; v0.y = acc[mt][nt][1] + bb.y;
            v1.x = acc[mt][nt][2] + bb.x; v1.y = acc[mt][nt][3] + bb.y;
            *(float2*)&C[(size_t)r * N + cc]       = v0;
            *(float2*)&C[(size_t)(r + 8) * N + cc] = v1;
        }
    }
}

// ---------------------------------------------------------------------------
// Flash attention on tensor cores.
// Block = (b, h, 128 q rows). 256 threads / 8 warps, each warp owns 16 q rows.
// KV tiles of 64. K and V kept in natural [j][d] layout (col-frag indexes it).
// ---------------------------------------------------------------------------
#define QS 68
#define KSS 68
#define VS 72
#define PSS 68

__global__ __launch_bounds__(256)
void attn_tc(const float* __restrict__ qkv, float* __restrict__ out)
{
    extern __shared__ unsigned sm[];
    unsigned* Qs = sm;                   // [128][QS]  Q (tf32, pre-scaled)
    unsigned* Ks = Qs + 128 * QS;        // [64][KSS]  K
    unsigned* Vs = Ks + 64 * KSS;        // [64][VS]   V
    unsigned* Ps = Vs + 64 * VS;         // [128][PSS] P (tf32)

    const int tid  = threadIdx.x;
    const int lane = tid & 31;
    const int w    = tid >> 5;
    const int g    = lane >> 2;
    const int qp   = lane & 3;
    const int q0   = blockIdx.x * 128;
    const int h    = blockIdx.y;
    const int b    = blockIdx.z;

    const size_t base = (size_t)b * S_LEN * QKV_DIM + (size_t)h * (3 * D_HEAD);

    // load Q tile (scale folded, tf32)
#pragma unroll
    for (int i = 0; i < 8; i++) {
        const int lin = tid + i * 256;
        const int r   = lin >> 4;
        const int d4  = (lin & 15) * 4;
        const float4 q = *(const float4*)&qkv[base + (size_t)(q0 + r) * QKV_DIM + d4];
        uint4 u;
        u.x = f2tf(q.x * 0.125f); u.y = f2tf(q.y * 0.125f);
        u.z = f2tf(q.z * 0.125f); u.w = f2tf(q.w * 0.125f);
        *(uint4*)&Qs[r * QS + d4] = u;
    }

    float o[8][4];
#pragma unroll
    for (int nt = 0; nt < 8; nt++)
#pragma unroll
        for (int r = 0; r < 4; r++) o[nt][r] = 0.f;
    float m0v = -INFINITY, m1v = -INFINITY, l0 = 0.f, l1 = 0.f;

    const int pr0 = w * 16 + g;

    for (int kt = 0; kt < S_LEN / 64; kt++) {
        __syncthreads();
        const int j0 = kt * 64;
#pragma unroll
        for (int i = 0; i < 4; i++) {
            const int lin = tid + i * 256;
            const int r   = lin >> 4;
            const int d4  = (lin & 15) * 4;
            const size_t rb = base + (size_t)(j0 + r) * QKV_DIM + d4;
            const float4 kk = *(const float4*)&qkv[rb + D_HEAD];
            const float4 vv = *(const float4*)&qkv[rb + 2 * D_HEAD];
            uint4 uk, uv;
            uk.x = f2tf(kk.x); uk.y = f2tf(kk.y); uk.z = f2tf(kk.z); uk.w = f2tf(kk.w);
            uv.x = f2tf(vv.x); uv.y = f2tf(vv.y); uv.z = f2tf(vv.z); uv.w = f2tf(vv.w);
            *(uint4*)&Ks[r * KSS + d4] = uk;
            *(uint4*)&Vs[r * VS  + d4] = uv;
        }
        __syncthreads();

        // ---- S = Q @ K^T ----
        float s[8][4];
#pragma unroll
        for (int nt = 0; nt < 8; nt++)
#pragma unroll
            for (int r = 0; r < 4; r++) s[nt][r] = 0.f;

#pragma unroll
        for (int ks = 0; ks < 8; ks++) {
            const int kb = ks * 8;
            unsigned aq[4];
            aq[0] = Qs[pr0 * QS + kb + qp];
            aq[1] = Qs[(pr0 + 8) * QS + kb + qp];
            aq[2] = Qs[pr0 * QS + kb + qp + 4];
            aq[3] = Qs[(pr0 + 8) * QS + kb + qp + 4];
#pragma unroll
            for (int nt = 0; nt < 8; nt++) {
                unsigned bk[2];
                const int c0 = nt * 8 + g;
                bk[0] = Ks[c0 * KSS + kb + qp];
                bk[1] = Ks[c0 * KSS + kb + qp + 4];
                mma8(s[nt], aq, bk);
            }
        }

        // ---- online softmax (rows g and g+8 of this warp's 16-row tile) ----
        float rm0 = s[0][0], rm1 = s[0][2];
#pragma unroll
        for (int nt = 0; nt < 8; nt++) {
            rm0 = fmaxf(rm0, fmaxf(s[nt][0], s[nt][1]));
            rm1 = fmaxf(rm1, fmaxf(s[nt][2], s[nt][3]));
        }
        rm0 = fmaxf(rm0, __shfl_xor_sync(0xffffffffu, rm0, 1));
        rm0 = fmaxf(rm0, __shfl_xor_sync(0xffffffffu, rm0, 2));
        rm1 = fmaxf(rm1, __shfl_xor_sync(0xffffffffu, rm1, 1));
        rm1 = fmaxf(rm1, __shfl_xor_sync(0xffffffffu, rm1, 2));

        const float mn0 = fmaxf(m0v, rm0);
        const float mn1 = fmaxf(m1v, rm1);
        const float corr0 = __expf(m0v - mn0);
        const float corr1 = __expf(m1v - mn1);
        m0v = mn0; m1v = mn1;

        float rs0 = 0.f, rs1 = 0.f;
#pragma unroll
        for (int nt = 0; nt < 8; nt++) {
            s[nt][0] = __expf(s[nt][0] - mn0);
            s[nt][1] = __expf(s[nt][1] - mn0);
            s[nt][2] = __expf(s[nt][2] - mn1);
            s[nt][3] = __expf(s[nt][3] - mn1);
            rs0 += s[nt][0] + s[nt][1];
            rs1 += s[nt][2] + s[nt][3];
        }
        rs0 += __shfl_xor_sync(0xffffffffu, rs0, 1);
        rs0 += __shfl_xor_sync(0xffffffffu, rs0, 2);
        rs1 += __shfl_xor_sync(0xffffffffu, rs1, 1);
        rs1 += __shfl_xor_sync(0xffffffffu, rs1, 2);
        l0 = l0 * corr0 + rs0;
        l1 = l1 * corr1 + rs1;

#pragma unroll
        for (int nt = 0; nt < 8; nt++) {
            o[nt][0] *= corr0; o[nt][1] *= corr0;
            o[nt][2] *= corr1; o[nt][3] *= corr1;
        }

        // stage P (warp-local)
#pragma unroll
        for (int nt = 0; nt < 8; nt++) {
            uint2 u0, u1;
            u0.x = f2tf(s[nt][0]); u0.y = f2tf(s[nt][1]);
            u1.x = f2tf(s[nt][2]); u1.y = f2tf(s[nt][3]);
            *(uint2*)&Ps[pr0 * PSS + nt * 8 + qp * 2]       = u0;
            *(uint2*)&Ps[(pr0 + 8) * PSS + nt * 8 + qp * 2] = u1;
        }
        __syncwarp();

        // ---- O += P @ V ----
#pragma unroll
        for (int ks = 0; ks < 8; ks++) {
            const int kb = ks * 8;
            unsigned ap[4];
            ap[0] = Ps[pr0 * PSS + kb + qp];
            ap[1] = Ps[(pr0 + 8) * PSS + kb + qp];
            ap[2] = Ps[pr0 * PSS + kb + qp + 4];
            ap[3] = Ps[(pr0 + 8) * PSS + kb + qp + 4];
#pragma unroll
            for (int nt = 0; nt < 8; nt++) {
                unsigned bv[2];
                bv[0] = Vs[(kb + qp) * VS + nt * 8 + g];
                bv[1] = Vs[(kb + qp + 4) * VS + nt * 8 + g];
                mma8(o[nt], ap, bv);
            }
        }
        __syncwarp();
    }

    // normalize + write [B,S,E]
    const float inv0 = 1.f / l0;
    const float inv1 = 1.f / l1;
    const int row0 = q0 + w * 16 + g;
#pragma unroll
    for (int nt = 0; nt < 8; nt++) {
        const int cc = h * D_HEAD + nt * 8 + qp * 2;
        float2 v0, v1;
        v0.x = o[nt][0] * inv0; v0.y = o[nt][1] * inv0;
        v1.x = o[nt][2] * inv1; v1.y = o[nt][3] * inv1;
        *(float2*)&out[((size_t)b * S_LEN + row0) * E_DIM + cc]     = v0;
        *(float2*)&out[((size_t)b * S_LEN + row0 + 8) * E_DIM + cc] = v1;
    }
}

// ---------------------------------------------------------------------------
extern "C" void kernel_launch(void* const* d_in, const int* in_sizes, int n_in,
                              void* d_out, int out_size)
{
    const float* x     = (const float*)d_in[0];
    const float* w_qkv = (const float*)d_in[1];
    const float* b_qkv = (const float*)d_in[2];
    const float* w_o   = (const float*)d_in[3];
    const float* b_o   = (const float*)d_in[4];
    float* out = (float*)d_out;

    float* qkv;  cudaGetSymbolAddress((void**)&qkv,  g_qkv);
    float* attn; cudaGetSymbolAddress((void**)&attn, g_attn);

    const int M = B_SZ * S_LEN;   // 4096

    // 1) QKV projection: [4096,1024] @ [3072,1024]^T
    gemm_tc<<<dim3(QKV_DIM / 128, M / 128), 256>>>(
        x, w_qkv, b_qkv, qkv, M, QKV_DIM, E_DIM);

    // 2) Flash attention (tensor core)
    const int attn_smem = (128 * QS + 64 * KSS + 64 * VS + 128 * PSS) * (int)sizeof(unsigned);
    static int attr_set = 0;
    if (!attr_set) {
        cudaFuncSetAttribute(attn_tc,
                             cudaFuncAttributeMaxDynamicSharedMemorySize, attn_smem);
        attr_set = 1;
    }
    attn_tc<<<dim3(S_LEN / 128, H_NUM, B_SZ), 256, attn_smem>>>(qkv, attn);

    // 3) Output projection: [4096,1024] @ [1024,1024]^T
    gemm_tc<<<dim3(E_DIM / 128, M / 128), 256>>>(
        attn, w_o, b_o, out, M, E_DIM, E_DIM);
}